// round 14
// baseline (speedup 1.0000x reference)
#include <cuda_runtime.h>
#include <cuda_fp16.h>
#include <cstdint>
#include <math.h>

#define BATCH 8
#define NN    2048
#define CC    256
#define RANK  16
#define QSTEPS 8
#define EPS_SPHERE 1e-6f
#define EPS_GN     1e-5f
#define CTA_PER_BATCH 16

// ---------------- device scratch (no allocation allowed) ----------------
__device__ __half g_Khi[(size_t)BATCH * NN * NN];     // 67 MB
__device__ __half g_Klo[(size_t)BATCH * NN * NN];     // 67 MB
__device__ __half g_xhb[2][(size_t)BATCH * NN * CC];  // fp16 x, ping/pong
__device__ float  g_ys [(size_t)BATCH * NN * CC];
__device__ float  g_x0 [(size_t)BATCH * NN * CC];
__device__ unsigned g_barr[BATCH];                    // per-batch barrier

// ---------------- helpers ----------------
__device__ __forceinline__ uint32_t smem_u32(const void* p) {
    uint32_t a;
    asm("{ .reg .u64 t; cvta.to.shared.u64 t, %1; cvt.u32.u64 %0, t; }" : "=r"(a) : "l"(p));
    return a;
}
__device__ __forceinline__ void cp16(uint32_t dst, const void* src) {
    asm volatile("cp.async.cg.shared.global [%0], [%1], 16;" :: "r"(dst), "l"(src));
}
#define CP_COMMIT() asm volatile("cp.async.commit_group;" ::: "memory")
#define CP_WAIT(n)  asm volatile("cp.async.wait_group %0;" :: "n"(n) : "memory")

#define LDSM_X4(r0,r1,r2,r3, a) \
    asm volatile("ldmatrix.sync.aligned.m8n8.x4.shared.b16 {%0,%1,%2,%3}, [%4];" \
        : "=r"(r0), "=r"(r1), "=r"(r2), "=r"(r3) : "r"(a))
#define LDSM_X4T(r0,r1,r2,r3, a) \
    asm volatile("ldmatrix.sync.aligned.m8n8.x4.trans.shared.b16 {%0,%1,%2,%3}, [%4];" \
        : "=r"(r0), "=r"(r1), "=r"(r2), "=r"(r3) : "r"(a))

#define MMA16816(d, a0,a1,a2,a3, b0,b1) \
    asm volatile("mma.sync.aligned.m16n8k16.row.col.f32.f16.f16.f32 " \
        "{%0,%1,%2,%3}, {%4,%5,%6,%7}, {%8,%9}, {%0,%1,%2,%3};" \
        : "+f"((d)[0]), "+f"((d)[1]), "+f"((d)[2]), "+f"((d)[3]) \
        : "r"(a0), "r"(a1), "r"(a2), "r"(a3), "r"(b0), "r"(b1))

// ---------------------------------------------------------------------------
// prologue: ONE kernel. gn (bid 0..511) and x0 (512..1535) FIRST so they
// overlap prep's DRAM stream; prep (1536..5631) with ping-pong staging and
// ONE sync per batch, tiles prefetched one batch ahead.
// ---------------------------------------------------------------------------
#define PRO_GN   512
#define PRO_X0   (PRO_GN + 1024)     // 1536
#define PRO_TOT  (PRO_X0 + 4096)     // 5632

__global__ __launch_bounds__(1024) void prologue(const float* __restrict__ sc,
                                                 const float* __restrict__ U,
                                                 const float* __restrict__ y,
                                                 const float* __restrict__ gw,
                                                 const float* __restrict__ gb,
                                                 const float* __restrict__ x)
{
    const int bid = blockIdx.x;
    const int tid = threadIdx.x;

    if (bid >= PRO_X0) {
        // ----- prep_K: symmetric tiles, ping-pong staging, 1 sync/batch -----
        const int tile = bid - PRO_X0;
        const int n0 = (tile >> 6) * 32, m0 = (tile & 63) * 32;
        if (m0 < n0) return;

        __shared__ float Un[32][17];
        __shared__ float Um[32][17];
        __shared__ float tU[2][32][33];   // direct  sc[n0+r, m0+c]
        __shared__ float tT[2][32][33];   // transp. sc[m0+r, n0+c]

        const int tx = tid & 31, ty = tid >> 5;

        if (tid < 512)      Un[tid >> 4][tid & 15] = U[(n0 + (tid >> 4)) * RANK + (tid & 15)];
        else { int u = tid - 512; Um[u >> 4][u & 15] = U[(m0 + (u >> 4)) * RANK + (u & 15)]; }

        // prefetch batch 0 tiles alongside U staging
        tU[0][ty][tx] = sc[(size_t)(n0 + ty) * NN + m0 + tx];
        tT[0][ty][tx] = sc[(size_t)(m0 + ty) * NN + n0 + tx];
        __syncthreads();

        float d1 = 0.f, d2 = 0.f;
#pragma unroll
        for (int k = 0; k < RANK; k++) {
            d1 += Un[ty][k] * Um[tx][k];   // sigma for (n0+ty, m0+tx)
            d2 += Um[ty][k] * Un[tx][k];   // sigma for (m0+ty, n0+tx)
        }
        const float a1 = 1.f / (1.f + __expf(-d1));
        const float a2 = 1.f / (1.f + __expf(-d2));

#pragma unroll 1
        for (int b = 0; b < BATCH; b++) {
            const int p = b & 1;
            const size_t base = (size_t)b * NN * NN;

            const float v1 = 0.5f * (tU[p][ty][tx] + tT[p][tx][ty]) * a1;
            __half hi = __float2half_rn(v1);
            __half lo = __float2half_rn(v1 - __half2float(hi));
            const size_t o1 = base + (size_t)(n0 + ty) * NN + m0 + tx;
            g_Khi[o1] = hi; g_Klo[o1] = lo;

            if (m0 != n0) {
                const float v2 = 0.5f * (tT[p][ty][tx] + tU[p][tx][ty]) * a2;
                __half hi2 = __float2half_rn(v2);
                __half lo2 = __float2half_rn(v2 - __half2float(hi2));
                const size_t o2 = base + (size_t)(m0 + ty) * NN + n0 + tx;
                g_Khi[o2] = hi2; g_Klo[o2] = lo2;
            }

            if (b + 1 < BATCH) {              // prefetch next batch
                const size_t nb = (size_t)(b + 1) * NN * NN;
                tU[p ^ 1][ty][tx] = sc[nb + (size_t)(n0 + ty) * NN + m0 + tx];
                tT[p ^ 1][ty][tx] = sc[nb + (size_t)(m0 + ty) * NN + n0 + tx];
                __syncthreads();
            }
        }
    } else if (bid < PRO_GN) {
        // ----- gn_sphere (R13-exact): GroupNorm (4ch x 2048) per (b,g) -----
        const int b = bid >> 6;
        const int g = bid & 63;
        const float* yg = y + ((size_t)b * CC + g * 4) * NN;

        float s = 0.f, s2 = 0.f;
        for (int i = tid; i < 4 * NN; i += 1024) { float v = yg[i]; s += v; s2 += v * v; }
        __shared__ float shs[32], shs2[32];
#pragma unroll
        for (int o = 16; o; o >>= 1) {
            s  += __shfl_down_sync(0xffffffffu, s,  o);
            s2 += __shfl_down_sync(0xffffffffu, s2, o);
        }
        if ((tid & 31) == 0) { shs[tid >> 5] = s; shs2[tid >> 5] = s2; }
        __syncthreads();
        if (tid == 0) {
            float ts = 0.f, ts2 = 0.f;
#pragma unroll
            for (int i = 0; i < 32; i++) { ts += shs[i]; ts2 += shs2[i]; }
            shs[0] = ts; shs2[0] = ts2;
        }
        __syncthreads();
        const float mu   = shs[0] * (1.f / (4 * NN));
        const float var  = shs2[0] * (1.f / (4 * NN)) - mu * mu;
        const float rstd = rsqrtf(var + EPS_GN);

        float w[4], bb[4];
#pragma unroll
        for (int j = 0; j < 4; j++) { w[j] = gw[g * 4 + j]; bb[j] = gb[g * 4 + j]; }

        for (int n = tid; n < NN; n += 1024) {
            float v[4];
#pragma unroll
            for (int j = 0; j < 4; j++)
                v[j] = (yg[j * NN + n] - mu) * rstd * w[j] + bb[j];
            float n2 = fmaxf(v[0]*v[0] + v[1]*v[1] + v[2]*v[2] + v[3]*v[3], EPS_SPHERE);
            float r = rsqrtf(n2);
            *(float4*)&g_ys[((size_t)b * NN + n) * CC + g * 4] =
                make_float4(v[0]*r, v[1]*r, v[2]*r, v[3]*r);
        }
    } else {
        // ----- sphere_x0: one thread per 4-group; resets barriers -----
        const int xb = bid - PRO_GN;                     // 0..1023
        if (xb == 0 && tid < BATCH) g_barr[tid] = 0;     // graph-replay reset
        const int idx = xb * 1024 + tid;
        float4 v = ((const float4*)x)[idx];
        float n2 = fmaxf(v.x*v.x + v.y*v.y + v.z*v.z + v.w*v.w, EPS_SPHERE);
        float rs = rsqrtf(n2);
        float o0 = v.x*rs, o1 = v.y*rs, o2 = v.z*rs, o3 = v.w*rs;
        ((float4*)g_x0)[idx] = make_float4(o0, o1, o2, o3);
        __half2 hh0 = __halves2half2(__float2half_rn(o0), __float2half_rn(o1));
        __half2 hh1 = __halves2half2(__float2half_rn(o2), __float2half_rn(o3));
        ((__half2*)g_xhb[0])[idx * 2]     = hh0;
        ((__half2*)g_xhb[0])[idx * 2 + 1] = hh1;
    }
}

// ---------------------------------------------------------------------------
// step_all (R13-exact, plateau 713-717 us): all 8 steps, persistent, 128 CTAs.
// M-tile 128 x N=256, BK=64; 16 warps, warp tile 64x32; B-frag double buffer;
// gmem prefetch after kk=0; per-batch grid barrier.
// ---------------------------------------------------------------------------
#define BK 64
#define OFF_AHI 0
#define OFF_ALO 16384
#define OFF_BHI 32768
#define STAGE   65536
#define NSTAGE  3
#define SMEM_TOTAL (NSTAGE * STAGE)   // 196608
#define CS_STRIDE 264

__global__ __launch_bounds__(512, 1) void step_all(float* __restrict__ out,
                                                   const float* __restrict__ omega,
                                                   const float* __restrict__ gammap)
{
    extern __shared__ __align__(16) char dsm[];
    const uint32_t smem = smem_u32(dsm);
    const int tid  = threadIdx.x;
    const int lane = tid & 31;
    const int wid  = tid >> 5;
    const int wm   = wid & 1;
    const int wn   = wid >> 1;
    const int b    = blockIdx.y;
    const int row0 = blockIdx.x * 128;
    const size_t E = (size_t)BATCH * NN * CC;

    const __half* __restrict__ Ah = g_Khi + (size_t)b * NN * NN + (size_t)row0 * NN;
    const __half* __restrict__ Al = g_Klo + (size_t)b * NN * NN + (size_t)row0 * NN;

    auto load_A = [&](int chunk, int buf) {
        const uint32_t sb = smem + buf * STAGE;
        const int k0 = chunk * BK;
#pragma unroll
        for (int it = 0; it < 2; it++) {
            int idx = tid + it * 512;
            int m = idx >> 3, ck = idx & 7;
            uint32_t off = m * 128 + ((ck ^ (m & 7)) << 4);
            const size_t go = (size_t)m * NN + k0 + ck * 8;
            cp16(sb + OFF_AHI + off, Ah + go);
            cp16(sb + OFF_ALO + off, Al + go);
        }
        CP_COMMIT();
    };
    auto load_B = [&](int chunk, int buf, const __half* __restrict__ Bh) {
        const uint32_t sb = smem + buf * STAGE;
        const int k0 = chunk * BK;
#pragma unroll
        for (int it = 0; it < 4; it++) {
            int idx = tid + it * 512;
            int kr = idx >> 5, nc = idx & 31;
            uint32_t off = kr * 512 + ((nc ^ (kr & 7)) << 4);
            const size_t go = (size_t)(k0 + kr) * CC + nc * 8;
            cp16(sb + OFF_BHI + off, Bh + go);
        }
        CP_COMMIT();
    };
    auto load_full = [&](int chunk, int buf, const __half* __restrict__ Bh) {
        const uint32_t sb = smem + buf * STAGE;
        const int k0 = chunk * BK;
#pragma unroll
        for (int it = 0; it < 2; it++) {
            int idx = tid + it * 512;
            int m = idx >> 3, ck = idx & 7;
            uint32_t off = m * 128 + ((ck ^ (m & 7)) << 4);
            const size_t go = (size_t)m * NN + k0 + ck * 8;
            cp16(sb + OFF_AHI + off, Ah + go);
            cp16(sb + OFF_ALO + off, Al + go);
        }
#pragma unroll
        for (int it = 0; it < 4; it++) {
            int idx = tid + it * 512;
            int kr = idx >> 5, nc = idx & 31;
            uint32_t off = kr * 512 + ((nc ^ (kr & 7)) << 4);
            const size_t go = (size_t)(k0 + kr) * CC + nc * 8;
            cp16(sb + OFF_BHI + off, Bh + go);
        }
        CP_COMMIT();
    };

    const float gamma = *gammap;
    const int c = lane * 8;
    const float og0 = fabsf(omega[(c >> 1) + 0]);
    const float og1 = fabsf(omega[(c >> 1) + 1]);
    const float og2 = fabsf(omega[(c >> 1) + 2]);
    const float og3 = fabsf(omega[(c >> 1) + 3]);
    const float* __restrict__ Yg = g_ys + (size_t)b * NN * CC;

    load_A(0, 0);
    load_A(1, 1);

#pragma unroll 1
    for (int q = 0; q < QSTEPS; q++) {
        const __half* __restrict__ Bh = g_xhb[q & 1] + (size_t)b * NN * CC;
        load_B(0, 0, Bh);
        load_B(1, 1, Bh);

        float acc[4][4][4];
#pragma unroll
        for (int i = 0; i < 4; i++)
#pragma unroll
            for (int j = 0; j < 4; j++)
#pragma unroll
                for (int k = 0; k < 4; k++) acc[i][j][k] = 0.f;

#pragma unroll 1
        for (int i = 0; i < 32; i++) {
            const int buf = i - (i / NSTAGE) * NSTAGE;
            if (i < 31) CP_WAIT(1); else CP_WAIT(0);
            __syncthreads();

            const uint32_t sA  = smem + buf * STAGE + OFF_AHI;
            const uint32_t sAl = smem + buf * STAGE + OFF_ALO;
            const uint32_t sB  = smem + buf * STAGE + OFF_BHI;

            uint32_t bhb[2][2][4];
#pragma unroll
            for (int nf2 = 0; nf2 < 2; nf2++) {
                const int kr = (lane & 15);
                const int nc = wn * 4 + nf2 * 2 + (lane >> 4);
                const uint32_t off = kr * 512 + ((nc ^ (kr & 7)) << 4);
                LDSM_X4T(bhb[0][nf2][0], bhb[0][nf2][1],
                         bhb[0][nf2][2], bhb[0][nf2][3], sB + off);
            }

#pragma unroll
            for (int kk = 0; kk < 4; kk++) {
                const int cur = kk & 1;
                if (kk < 3) {
#pragma unroll
                    for (int nf2 = 0; nf2 < 2; nf2++) {
                        const int kr = (kk + 1) * 16 + (lane & 15);
                        const int nc = wn * 4 + nf2 * 2 + (lane >> 4);
                        const uint32_t off = kr * 512 + ((nc ^ (kr & 7)) << 4);
                        LDSM_X4T(bhb[cur ^ 1][nf2][0], bhb[cur ^ 1][nf2][1],
                                 bhb[cur ^ 1][nf2][2], bhb[cur ^ 1][nf2][3], sB + off);
                    }
                }
#pragma unroll
                for (int mf = 0; mf < 4; mf++) {
                    const int m = wm * 64 + mf * 16 + (lane & 15);
                    const int kc = kk * 2 + (lane >> 4);
                    const uint32_t off = m * 128 + ((kc ^ (m & 7)) << 4);
                    uint32_t ah0, ah1, ah2, ah3, al0, al1, al2, al3;
                    LDSM_X4(ah0, ah1, ah2, ah3, sA  + off);
                    LDSM_X4(al0, al1, al2, al3, sAl + off);
#pragma unroll
                    for (int nf2 = 0; nf2 < 2; nf2++) {
#pragma unroll
                        for (int j = 0; j < 2; j++) {
                            float* d = acc[mf][nf2 * 2 + j];
                            MMA16816(d, ah0, ah1, ah2, ah3,
                                     bhb[cur][nf2][j*2], bhb[cur][nf2][j*2+1]);
                            MMA16816(d, al0, al1, al2, al3,
                                     bhb[cur][nf2][j*2], bhb[cur][nf2][j*2+1]);
                        }
                    }
                }
                if (kk == 0 && i + 2 < 32) {
                    int nb = (i + 2) - ((i + 2) / NSTAGE) * NSTAGE;
                    load_full(i + 2, nb, Bh);
                }
            }
        }
        __syncthreads();

        float* cs = (float*)dsm;
#pragma unroll
        for (int mf = 0; mf < 4; mf++)
#pragma unroll
            for (int mh = 0; mh < 2; mh++)
#pragma unroll
                for (int nf = 0; nf < 4; nf++) {
                    const int row = wm * 64 + mf * 16 + mh * 8 + (lane >> 2);
                    const int col = wn * 32 + nf * 8 + (lane & 3) * 2;
                    *(float2*)&cs[row * CS_STRIDE + col] =
                        make_float2(acc[mf][nf][mh * 2], acc[mf][nf][mh * 2 + 1]);
                }
        __syncthreads();

        const float* __restrict__ Xg = (q == 0 ? g_x0 : out + (size_t)(q - 1) * E)
                                       + (size_t)b * NN * CC;
        float* __restrict__ Og = out + (size_t)q * E + (size_t)b * NN * CC;
        __half* __restrict__ XHg = g_xhb[(q + 1) & 1] + (size_t)b * NN * CC;

#pragma unroll 1
        for (int rr = 0; rr < 8; rr++) {
            const int lr = wid * 8 + rr;
            const size_t goff = (size_t)(row0 + lr) * CC + c;
            float4 k0 = *(const float4*)&cs[lr * CS_STRIDE + c];
            float4 k1 = *(const float4*)&cs[lr * CS_STRIDE + c + 4];
            float4 x0 = *(const float4*)&Xg[goff];
            float4 x1 = *(const float4*)&Xg[goff + 4];
            float4 y0 = *(const float4*)&Yg[goff];
            float4 y1 = *(const float4*)&Yg[goff + 4];

            float ox[8];
            {
                float f0 = k0.x + y0.x, f1 = k0.y + y0.y, f2 = k0.z + y0.z, f3 = k0.w + y0.w;
                float sim = x0.x*f0 + x0.y*f1 + x0.z*f2 + x0.w*f3;
                float d0 =  og0 * x0.y + (f0 - sim * x0.x);
                float d1 = -og0 * x0.x + (f1 - sim * x0.y);
                float d2 =  og1 * x0.w + (f2 - sim * x0.z);
                float d3 = -og1 * x0.z + (f3 - sim * x0.w);
                float u0 = x0.x + gamma * d0, u1 = x0.y + gamma * d1;
                float u2 = x0.z + gamma * d2, u3 = x0.w + gamma * d3;
                float rs = rsqrtf(fmaxf(u0*u0 + u1*u1 + u2*u2 + u3*u3, EPS_SPHERE));
                ox[0] = u0*rs; ox[1] = u1*rs; ox[2] = u2*rs; ox[3] = u3*rs;
            }
            {
                float f0 = k1.x + y1.x, f1 = k1.y + y1.y, f2 = k1.z + y1.z, f3 = k1.w + y1.w;
                float sim = x1.x*f0 + x1.y*f1 + x1.z*f2 + x1.w*f3;
                float d0 =  og2 * x1.y + (f0 - sim * x1.x);
                float d1 = -og2 * x1.x + (f1 - sim * x1.y);
                float d2 =  og3 * x1.w + (f2 - sim * x1.z);
                float d3 = -og3 * x1.z + (f3 - sim * x1.w);
                float u0 = x1.x + gamma * d0, u1 = x1.y + gamma * d1;
                float u2 = x1.z + gamma * d2, u3 = x1.w + gamma * d3;
                float rs = rsqrtf(fmaxf(u0*u0 + u1*u1 + u2*u2 + u3*u3, EPS_SPHERE));
                ox[4] = u0*rs; ox[5] = u1*rs; ox[6] = u2*rs; ox[7] = u3*rs;
            }
            *(float4*)&Og[goff]     = make_float4(ox[0], ox[1], ox[2], ox[3]);
            *(float4*)&Og[goff + 4] = make_float4(ox[4], ox[5], ox[6], ox[7]);

            if (q < QSTEPS - 1) {
                uint32_t hw[4];
#pragma unroll
                for (int j = 0; j < 4; j++) {
                    __half2 p = __halves2half2(__float2half_rn(ox[2*j]),
                                               __float2half_rn(ox[2*j+1]));
                    hw[j] = *(uint32_t*)&p;
                }
                *(uint4*)&XHg[goff] = make_uint4(hw[0], hw[1], hw[2], hw[3]);
            }
        }

        if (q < QSTEPS - 1) {
            __syncthreads();
            load_A(0, 0);
            load_A(1, 1);
            if (tid == 0) {                  // per-batch barrier (16 CTAs)
                unsigned* bar = &g_barr[b];
                asm volatile("red.release.gpu.global.add.u32 [%0], 1;"
                             :: "l"(bar) : "memory");
                const unsigned target = (unsigned)(q + 1) * CTA_PER_BATCH;
                unsigned v;
                do {
                    asm volatile("ld.acquire.gpu.global.u32 %0, [%1];"
                                 : "=r"(v) : "l"(bar) : "memory");
                } while (v < target);
            }
            __syncthreads();
        }
    }
}

// ---------------------------------------------------------------------------
// Launch. Inputs: x, y, sc, U, omega_param, gn_w, gn_b, gamma, Q.
// Output: xs [Q=8, B, N, C] fp32.
// ---------------------------------------------------------------------------
extern "C" void kernel_launch(void* const* d_in, const int* in_sizes, int n_in,
                              void* d_out, int out_size)
{
    const float* x     = (const float*)d_in[0];
    const float* y     = (const float*)d_in[1];
    const float* sc    = (const float*)d_in[2];
    const float* U     = (const float*)d_in[3];
    const float* omega = (const float*)d_in[4];
    const float* gw    = (const float*)d_in[5];
    const float* gb    = (const float*)d_in[6];
    const float* gamma = (const float*)d_in[7];
    float* out = (float*)d_out;

    static int attr_set = 0;
    if (!attr_set) {
        cudaFuncSetAttribute(step_all, cudaFuncAttributeMaxDynamicSharedMemorySize,
                             SMEM_TOTAL);
        attr_set = 1;
    }

    prologue<<<PRO_TOT, 1024>>>(sc, U, y, gw, gb, x);
    step_all<<<dim3(16, BATCH), 512, SMEM_TOTAL>>>(out, omega, gamma);
}

// round 15
// speedup vs baseline: 1.0108x; 1.0108x over previous
#include <cuda_runtime.h>
#include <cuda_fp16.h>
#include <cstdint>
#include <math.h>

#define BATCH 8
#define NN    2048
#define CC    256
#define RANK  16
#define QSTEPS 8
#define EPS_SPHERE 1e-6f
#define EPS_GN     1e-5f
#define CTA_PER_BATCH 16

// ---------------- device scratch (no allocation allowed) ----------------
__device__ __half g_Khi[(size_t)BATCH * NN * NN];     // 67 MB
__device__ __half g_Klo[(size_t)BATCH * NN * NN];     // 67 MB
__device__ __half g_xhb[2][(size_t)BATCH * NN * CC];  // fp16 x, ping/pong
__device__ float  g_ys [(size_t)BATCH * NN * CC];
__device__ float  g_x0 [(size_t)BATCH * NN * CC];
__device__ unsigned g_barr[BATCH];                    // per-batch barrier

// ---------------- helpers ----------------
__device__ __forceinline__ uint32_t smem_u32(const void* p) {
    uint32_t a;
    asm("{ .reg .u64 t; cvta.to.shared.u64 t, %1; cvt.u32.u64 %0, t; }" : "=r"(a) : "l"(p));
    return a;
}
__device__ __forceinline__ void cp16(uint32_t dst, const void* src) {
    asm volatile("cp.async.cg.shared.global [%0], [%1], 16;" :: "r"(dst), "l"(src));
}
#define CP_COMMIT() asm volatile("cp.async.commit_group;" ::: "memory")
#define CP_WAIT(n)  asm volatile("cp.async.wait_group %0;" :: "n"(n) : "memory")

#define LDSM_X4(r0,r1,r2,r3, a) \
    asm volatile("ldmatrix.sync.aligned.m8n8.x4.shared.b16 {%0,%1,%2,%3}, [%4];" \
        : "=r"(r0), "=r"(r1), "=r"(r2), "=r"(r3) : "r"(a))
#define LDSM_X4T(r0,r1,r2,r3, a) \
    asm volatile("ldmatrix.sync.aligned.m8n8.x4.trans.shared.b16 {%0,%1,%2,%3}, [%4];" \
        : "=r"(r0), "=r"(r1), "=r"(r2), "=r"(r3) : "r"(a))

#define MMA16816(d, a0,a1,a2,a3, b0,b1) \
    asm volatile("mma.sync.aligned.m16n8k16.row.col.f32.f16.f16.f32 " \
        "{%0,%1,%2,%3}, {%4,%5,%6,%7}, {%8,%9}, {%0,%1,%2,%3};" \
        : "+f"((d)[0]), "+f"((d)[1]), "+f"((d)[2]), "+f"((d)[3]) \
        : "r"(a0), "r"(a1), "r"(a2), "r"(a3), "r"(b0), "r"(b1))

// ---------------------------------------------------------------------------
// prologue: ONE kernel. gn (bid 0..511) and x0 (512..1535) scheduled FIRST so
// their ~16 MB overlaps prep's DRAM stream; prep (1536..5631) is R13's
// byte-identical serial-batch version (best measured).
// ---------------------------------------------------------------------------
#define PRO_GN   512
#define PRO_X0   (PRO_GN + 1024)     // 1536
#define PRO_TOT  (PRO_X0 + 4096)     // 5632

__global__ __launch_bounds__(1024) void prologue(const float* __restrict__ sc,
                                                 const float* __restrict__ U,
                                                 const float* __restrict__ y,
                                                 const float* __restrict__ gw,
                                                 const float* __restrict__ gb,
                                                 const float* __restrict__ x)
{
    const int bid = blockIdx.x;
    const int tid = threadIdx.x;

    if (bid >= PRO_X0) {
        // ----- prep_K (R13-exact): serial batch loop, symmetric tiles -----
        const int tile = bid - PRO_X0;
        const int n0 = (tile >> 6) * 32, m0 = (tile & 63) * 32;
        if (m0 < n0) return;

        __shared__ float Un[32][17];
        __shared__ float Um[32][17];
        __shared__ float tT[32][33];
        __shared__ float vS[32][33];

        const int tx = tid & 31, ty = tid >> 5;

        if (tid < 512)      Un[tid >> 4][tid & 15] = U[(n0 + (tid >> 4)) * RANK + (tid & 15)];
        else { int u = tid - 512; Um[u >> 4][u & 15] = U[(m0 + (u >> 4)) * RANK + (u & 15)]; }
        __syncthreads();

        float d = 0.f;
#pragma unroll
        for (int k = 0; k < RANK; k++) d += Un[ty][k] * Um[tx][k];
        const float a = 1.f / (1.f + __expf(-d));

        const int n = n0 + ty, m = m0 + tx;
#pragma unroll 1
        for (int b = 0; b < BATCH; b++) {
            const size_t base = (size_t)b * NN * NN;
            tT[ty][tx] = sc[base + (size_t)(m0 + ty) * NN + (n0 + tx)];
            __syncthreads();
            const float v = 0.5f * (sc[base + (size_t)n * NN + m] + tT[tx][ty]) * a;
            __half hi = __float2half_rn(v);
            __half lo = __float2half_rn(v - __half2float(hi));
            const size_t o1 = base + (size_t)n * NN + m;
            g_Khi[o1] = hi; g_Klo[o1] = lo;
            vS[ty][tx] = v;
            __syncthreads();
            if (m0 != n0) {
                const float vt = vS[tx][ty];
                __half hi2 = __float2half_rn(vt);
                __half lo2 = __float2half_rn(vt - __half2float(hi2));
                const size_t o2 = base + (size_t)(m0 + ty) * NN + (n0 + tx);
                g_Khi[o2] = hi2; g_Klo[o2] = lo2;
            }
            __syncthreads();
        }
    } else if (bid < PRO_GN) {
        // ----- gn_sphere (R13-exact): GroupNorm (4ch x 2048) per (b,g) -----
        const int b = bid >> 6;
        const int g = bid & 63;
        const float* yg = y + ((size_t)b * CC + g * 4) * NN;

        float s = 0.f, s2 = 0.f;
        for (int i = tid; i < 4 * NN; i += 1024) { float v = yg[i]; s += v; s2 += v * v; }
        __shared__ float shs[32], shs2[32];
#pragma unroll
        for (int o = 16; o; o >>= 1) {
            s  += __shfl_down_sync(0xffffffffu, s,  o);
            s2 += __shfl_down_sync(0xffffffffu, s2, o);
        }
        if ((tid & 31) == 0) { shs[tid >> 5] = s; shs2[tid >> 5] = s2; }
        __syncthreads();
        if (tid == 0) {
            float ts = 0.f, ts2 = 0.f;
#pragma unroll
            for (int i = 0; i < 32; i++) { ts += shs[i]; ts2 += shs2[i]; }
            shs[0] = ts; shs2[0] = ts2;
        }
        __syncthreads();
        const float mu   = shs[0] * (1.f / (4 * NN));
        const float var  = shs2[0] * (1.f / (4 * NN)) - mu * mu;
        const float rstd = rsqrtf(var + EPS_GN);

        float w[4], bb[4];
#pragma unroll
        for (int j = 0; j < 4; j++) { w[j] = gw[g * 4 + j]; bb[j] = gb[g * 4 + j]; }

        for (int n = tid; n < NN; n += 1024) {
            float v[4];
#pragma unroll
            for (int j = 0; j < 4; j++)
                v[j] = (yg[j * NN + n] - mu) * rstd * w[j] + bb[j];
            float n2 = fmaxf(v[0]*v[0] + v[1]*v[1] + v[2]*v[2] + v[3]*v[3], EPS_SPHERE);
            float r = rsqrtf(n2);
            *(float4*)&g_ys[((size_t)b * NN + n) * CC + g * 4] =
                make_float4(v[0]*r, v[1]*r, v[2]*r, v[3]*r);
        }
    } else {
        // ----- sphere_x0: one thread per 4-group; resets barriers -----
        const int xb = bid - PRO_GN;                     // 0..1023
        if (xb == 0 && tid < BATCH) g_barr[tid] = 0;     // graph-replay reset
        const int idx = xb * 1024 + tid;
        float4 v = ((const float4*)x)[idx];
        float n2 = fmaxf(v.x*v.x + v.y*v.y + v.z*v.z + v.w*v.w, EPS_SPHERE);
        float rs = rsqrtf(n2);
        float o0 = v.x*rs, o1 = v.y*rs, o2 = v.z*rs, o3 = v.w*rs;
        ((float4*)g_x0)[idx] = make_float4(o0, o1, o2, o3);
        __half2 hh0 = __halves2half2(__float2half_rn(o0), __float2half_rn(o1));
        __half2 hh1 = __halves2half2(__float2half_rn(o2), __float2half_rn(o3));
        ((__half2*)g_xhb[0])[idx * 2]     = hh0;
        ((__half2*)g_xhb[0])[idx * 2 + 1] = hh1;
    }
}

// ---------------------------------------------------------------------------
// step_all (R13-exact, plateau 712-717 us): all 8 steps, persistent, 128 CTAs.
// M-tile 128 x N=256, BK=64; 16 warps, warp tile 64x32; B-frag double buffer;
// gmem prefetch after kk=0; per-batch grid barrier.
// ---------------------------------------------------------------------------
#define BK 64
#define OFF_AHI 0
#define OFF_ALO 16384
#define OFF_BHI 32768
#define STAGE   65536
#define NSTAGE  3
#define SMEM_TOTAL (NSTAGE * STAGE)   // 196608
#define CS_STRIDE 264

__global__ __launch_bounds__(512, 1) void step_all(float* __restrict__ out,
                                                   const float* __restrict__ omega,
                                                   const float* __restrict__ gammap)
{
    extern __shared__ __align__(16) char dsm[];
    const uint32_t smem = smem_u32(dsm);
    const int tid  = threadIdx.x;
    const int lane = tid & 31;
    const int wid  = tid >> 5;
    const int wm   = wid & 1;
    const int wn   = wid >> 1;
    const int b    = blockIdx.y;
    const int row0 = blockIdx.x * 128;
    const size_t E = (size_t)BATCH * NN * CC;

    const __half* __restrict__ Ah = g_Khi + (size_t)b * NN * NN + (size_t)row0 * NN;
    const __half* __restrict__ Al = g_Klo + (size_t)b * NN * NN + (size_t)row0 * NN;

    auto load_A = [&](int chunk, int buf) {
        const uint32_t sb = smem + buf * STAGE;
        const int k0 = chunk * BK;
#pragma unroll
        for (int it = 0; it < 2; it++) {
            int idx = tid + it * 512;
            int m = idx >> 3, ck = idx & 7;
            uint32_t off = m * 128 + ((ck ^ (m & 7)) << 4);
            const size_t go = (size_t)m * NN + k0 + ck * 8;
            cp16(sb + OFF_AHI + off, Ah + go);
            cp16(sb + OFF_ALO + off, Al + go);
        }
        CP_COMMIT();
    };
    auto load_B = [&](int chunk, int buf, const __half* __restrict__ Bh) {
        const uint32_t sb = smem + buf * STAGE;
        const int k0 = chunk * BK;
#pragma unroll
        for (int it = 0; it < 4; it++) {
            int idx = tid + it * 512;
            int kr = idx >> 5, nc = idx & 31;
            uint32_t off = kr * 512 + ((nc ^ (kr & 7)) << 4);
            const size_t go = (size_t)(k0 + kr) * CC + nc * 8;
            cp16(sb + OFF_BHI + off, Bh + go);
        }
        CP_COMMIT();
    };
    auto load_full = [&](int chunk, int buf, const __half* __restrict__ Bh) {
        const uint32_t sb = smem + buf * STAGE;
        const int k0 = chunk * BK;
#pragma unroll
        for (int it = 0; it < 2; it++) {
            int idx = tid + it * 512;
            int m = idx >> 3, ck = idx & 7;
            uint32_t off = m * 128 + ((ck ^ (m & 7)) << 4);
            const size_t go = (size_t)m * NN + k0 + ck * 8;
            cp16(sb + OFF_AHI + off, Ah + go);
            cp16(sb + OFF_ALO + off, Al + go);
        }
#pragma unroll
        for (int it = 0; it < 4; it++) {
            int idx = tid + it * 512;
            int kr = idx >> 5, nc = idx & 31;
            uint32_t off = kr * 512 + ((nc ^ (kr & 7)) << 4);
            const size_t go = (size_t)(k0 + kr) * CC + nc * 8;
            cp16(sb + OFF_BHI + off, Bh + go);
        }
        CP_COMMIT();
    };

    const float gamma = *gammap;
    const int c = lane * 8;
    const float og0 = fabsf(omega[(c >> 1) + 0]);
    const float og1 = fabsf(omega[(c >> 1) + 1]);
    const float og2 = fabsf(omega[(c >> 1) + 2]);
    const float og3 = fabsf(omega[(c >> 1) + 3]);
    const float* __restrict__ Yg = g_ys + (size_t)b * NN * CC;

    load_A(0, 0);
    load_A(1, 1);

#pragma unroll 1
    for (int q = 0; q < QSTEPS; q++) {
        const __half* __restrict__ Bh = g_xhb[q & 1] + (size_t)b * NN * CC;
        load_B(0, 0, Bh);
        load_B(1, 1, Bh);

        float acc[4][4][4];
#pragma unroll
        for (int i = 0; i < 4; i++)
#pragma unroll
            for (int j = 0; j < 4; j++)
#pragma unroll
                for (int k = 0; k < 4; k++) acc[i][j][k] = 0.f;

#pragma unroll 1
        for (int i = 0; i < 32; i++) {
            const int buf = i - (i / NSTAGE) * NSTAGE;
            if (i < 31) CP_WAIT(1); else CP_WAIT(0);
            __syncthreads();

            const uint32_t sA  = smem + buf * STAGE + OFF_AHI;
            const uint32_t sAl = smem + buf * STAGE + OFF_ALO;
            const uint32_t sB  = smem + buf * STAGE + OFF_BHI;

            uint32_t bhb[2][2][4];
#pragma unroll
            for (int nf2 = 0; nf2 < 2; nf2++) {
                const int kr = (lane & 15);
                const int nc = wn * 4 + nf2 * 2 + (lane >> 4);
                const uint32_t off = kr * 512 + ((nc ^ (kr & 7)) << 4);
                LDSM_X4T(bhb[0][nf2][0], bhb[0][nf2][1],
                         bhb[0][nf2][2], bhb[0][nf2][3], sB + off);
            }

#pragma unroll
            for (int kk = 0; kk < 4; kk++) {
                const int cur = kk & 1;
                if (kk < 3) {
#pragma unroll
                    for (int nf2 = 0; nf2 < 2; nf2++) {
                        const int kr = (kk + 1) * 16 + (lane & 15);
                        const int nc = wn * 4 + nf2 * 2 + (lane >> 4);
                        const uint32_t off = kr * 512 + ((nc ^ (kr & 7)) << 4);
                        LDSM_X4T(bhb[cur ^ 1][nf2][0], bhb[cur ^ 1][nf2][1],
                                 bhb[cur ^ 1][nf2][2], bhb[cur ^ 1][nf2][3], sB + off);
                    }
                }
#pragma unroll
                for (int mf = 0; mf < 4; mf++) {
                    const int m = wm * 64 + mf * 16 + (lane & 15);
                    const int kc = kk * 2 + (lane >> 4);
                    const uint32_t off = m * 128 + ((kc ^ (m & 7)) << 4);
                    uint32_t ah0, ah1, ah2, ah3, al0, al1, al2, al3;
                    LDSM_X4(ah0, ah1, ah2, ah3, sA  + off);
                    LDSM_X4(al0, al1, al2, al3, sAl + off);
#pragma unroll
                    for (int nf2 = 0; nf2 < 2; nf2++) {
#pragma unroll
                        for (int j = 0; j < 2; j++) {
                            float* d = acc[mf][nf2 * 2 + j];
                            MMA16816(d, ah0, ah1, ah2, ah3,
                                     bhb[cur][nf2][j*2], bhb[cur][nf2][j*2+1]);
                            MMA16816(d, al0, al1, al2, al3,
                                     bhb[cur][nf2][j*2], bhb[cur][nf2][j*2+1]);
                        }
                    }
                }
                if (kk == 0 && i + 2 < 32) {
                    int nb = (i + 2) - ((i + 2) / NSTAGE) * NSTAGE;
                    load_full(i + 2, nb, Bh);
                }
            }
        }
        __syncthreads();

        float* cs = (float*)dsm;
#pragma unroll
        for (int mf = 0; mf < 4; mf++)
#pragma unroll
            for (int mh = 0; mh < 2; mh++)
#pragma unroll
                for (int nf = 0; nf < 4; nf++) {
                    const int row = wm * 64 + mf * 16 + mh * 8 + (lane >> 2);
                    const int col = wn * 32 + nf * 8 + (lane & 3) * 2;
                    *(float2*)&cs[row * CS_STRIDE + col] =
                        make_float2(acc[mf][nf][mh * 2], acc[mf][nf][mh * 2 + 1]);
                }
        __syncthreads();

        const float* __restrict__ Xg = (q == 0 ? g_x0 : out + (size_t)(q - 1) * E)
                                       + (size_t)b * NN * CC;
        float* __restrict__ Og = out + (size_t)q * E + (size_t)b * NN * CC;
        __half* __restrict__ XHg = g_xhb[(q + 1) & 1] + (size_t)b * NN * CC;

#pragma unroll 1
        for (int rr = 0; rr < 8; rr++) {
            const int lr = wid * 8 + rr;
            const size_t goff = (size_t)(row0 + lr) * CC + c;
            float4 k0 = *(const float4*)&cs[lr * CS_STRIDE + c];
            float4 k1 = *(const float4*)&cs[lr * CS_STRIDE + c + 4];
            float4 x0 = *(const float4*)&Xg[goff];
            float4 x1 = *(const float4*)&Xg[goff + 4];
            float4 y0 = *(const float4*)&Yg[goff];
            float4 y1 = *(const float4*)&Yg[goff + 4];

            float ox[8];
            {
                float f0 = k0.x + y0.x, f1 = k0.y + y0.y, f2 = k0.z + y0.z, f3 = k0.w + y0.w;
                float sim = x0.x*f0 + x0.y*f1 + x0.z*f2 + x0.w*f3;
                float d0 =  og0 * x0.y + (f0 - sim * x0.x);
                float d1 = -og0 * x0.x + (f1 - sim * x0.y);
                float d2 =  og1 * x0.w + (f2 - sim * x0.z);
                float d3 = -og1 * x0.z + (f3 - sim * x0.w);
                float u0 = x0.x + gamma * d0, u1 = x0.y + gamma * d1;
                float u2 = x0.z + gamma * d2, u3 = x0.w + gamma * d3;
                float rs = rsqrtf(fmaxf(u0*u0 + u1*u1 + u2*u2 + u3*u3, EPS_SPHERE));
                ox[0] = u0*rs; ox[1] = u1*rs; ox[2] = u2*rs; ox[3] = u3*rs;
            }
            {
                float f0 = k1.x + y1.x, f1 = k1.y + y1.y, f2 = k1.z + y1.z, f3 = k1.w + y1.w;
                float sim = x1.x*f0 + x1.y*f1 + x1.z*f2 + x1.w*f3;
                float d0 =  og2 * x1.y + (f0 - sim * x1.x);
                float d1 = -og2 * x1.x + (f1 - sim * x1.y);
                float d2 =  og3 * x1.w + (f2 - sim * x1.z);
                float d3 = -og3 * x1.z + (f3 - sim * x1.w);
                float u0 = x1.x + gamma * d0, u1 = x1.y + gamma * d1;
                float u2 = x1.z + gamma * d2, u3 = x1.w + gamma * d3;
                float rs = rsqrtf(fmaxf(u0*u0 + u1*u1 + u2*u2 + u3*u3, EPS_SPHERE));
                ox[4] = u0*rs; ox[5] = u1*rs; ox[6] = u2*rs; ox[7] = u3*rs;
            }
            *(float4*)&Og[goff]     = make_float4(ox[0], ox[1], ox[2], ox[3]);
            *(float4*)&Og[goff + 4] = make_float4(ox[4], ox[5], ox[6], ox[7]);

            if (q < QSTEPS - 1) {
                uint32_t hw[4];
#pragma unroll
                for (int j = 0; j < 4; j++) {
                    __half2 p = __halves2half2(__float2half_rn(ox[2*j]),
                                               __float2half_rn(ox[2*j+1]));
                    hw[j] = *(uint32_t*)&p;
                }
                *(uint4*)&XHg[goff] = make_uint4(hw[0], hw[1], hw[2], hw[3]);
            }
        }

        if (q < QSTEPS - 1) {
            __syncthreads();
            load_A(0, 0);
            load_A(1, 1);
            if (tid == 0) {                  // per-batch barrier (16 CTAs)
                unsigned* bar = &g_barr[b];
                asm volatile("red.release.gpu.global.add.u32 [%0], 1;"
                             :: "l"(bar) : "memory");
                const unsigned target = (unsigned)(q + 1) * CTA_PER_BATCH;
                unsigned v;
                do {
                    asm volatile("ld.acquire.gpu.global.u32 %0, [%1];"
                                 : "=r"(v) : "l"(bar) : "memory");
                } while (v < target);
            }
            __syncthreads();
        }
    }
}

// ---------------------------------------------------------------------------
// Launch. Inputs: x, y, sc, U, omega_param, gn_w, gn_b, gamma, Q.
// Output: xs [Q=8, B, N, C] fp32.
// ---------------------------------------------------------------------------
extern "C" void kernel_launch(void* const* d_in, const int* in_sizes, int n_in,
                              void* d_out, int out_size)
{
    const float* x     = (const float*)d_in[0];
    const float* y     = (const float*)d_in[1];
    const float* sc    = (const float*)d_in[2];
    const float* U     = (const float*)d_in[3];
    const float* omega = (const float*)d_in[4];
    const float* gw    = (const float*)d_in[5];
    const float* gb    = (const float*)d_in[6];
    const float* gamma = (const float*)d_in[7];
    float* out = (float*)d_out;

    static int attr_set = 0;
    if (!attr_set) {
        cudaFuncSetAttribute(step_all, cudaFuncAttributeMaxDynamicSharedMemorySize,
                             SMEM_TOTAL);
        attr_set = 1;
    }

    prologue<<<PRO_TOT, 1024>>>(sc, U, y, gw, gb, x);
    step_all<<<dim3(16, BATCH), 512, SMEM_TOTAL>>>(out, omega, gamma);
}

// round 16
// speedup vs baseline: 1.0232x; 1.0122x over previous
#include <cuda_runtime.h>
#include <cuda_fp16.h>
#include <cstdint>
#include <math.h>

#define BATCH 8
#define NN    2048
#define CC    256
#define RANK  16
#define QSTEPS 8
#define EPS_SPHERE 1e-6f
#define EPS_GN     1e-5f
#define CTA_PER_BATCH 16

// ---------------- device scratch (no allocation allowed) ----------------
__device__ __half g_Khi[(size_t)BATCH * NN * NN];     // 67 MB
__device__ __half g_Klo[(size_t)BATCH * NN * NN];     // 67 MB
__device__ __half g_xhb[2][(size_t)BATCH * NN * CC];  // fp16 x, ping/pong
__device__ float  g_ys [(size_t)BATCH * NN * CC];
__device__ float  g_x0 [(size_t)BATCH * NN * CC];
__device__ unsigned g_barr[BATCH];                    // per-batch barrier

// ---------------- helpers ----------------
__device__ __forceinline__ uint32_t smem_u32(const void* p) {
    uint32_t a;
    asm("{ .reg .u64 t; cvta.to.shared.u64 t, %1; cvt.u32.u64 %0, t; }" : "=r"(a) : "l"(p));
    return a;
}
__device__ __forceinline__ void cp16(uint32_t dst, const void* src) {
    asm volatile("cp.async.cg.shared.global [%0], [%1], 16;" :: "r"(dst), "l"(src));
}
#define CP_COMMIT() asm volatile("cp.async.commit_group;" ::: "memory")
#define CP_WAIT(n)  asm volatile("cp.async.wait_group %0;" :: "n"(n) : "memory")

#define LDSM_X4(r0,r1,r2,r3, a) \
    asm volatile("ldmatrix.sync.aligned.m8n8.x4.shared.b16 {%0,%1,%2,%3}, [%4];" \
        : "=r"(r0), "=r"(r1), "=r"(r2), "=r"(r3) : "r"(a))
#define LDSM_X4T(r0,r1,r2,r3, a) \
    asm volatile("ldmatrix.sync.aligned.m8n8.x4.trans.shared.b16 {%0,%1,%2,%3}, [%4];" \
        : "=r"(r0), "=r"(r1), "=r"(r2), "=r"(r3) : "r"(a))

#define MMA16816(d, a0,a1,a2,a3, b0,b1) \
    asm volatile("mma.sync.aligned.m16n8k16.row.col.f32.f16.f16.f32 " \
        "{%0,%1,%2,%3}, {%4,%5,%6,%7}, {%8,%9}, {%0,%1,%2,%3};" \
        : "+f"((d)[0]), "+f"((d)[1]), "+f"((d)[2]), "+f"((d)[3]) \
        : "r"(a0), "r"(a1), "r"(a2), "r"(a3), "r"(b0), "r"(b1))

// ---------------------------------------------------------------------------
// prologue: ONE kernel. prep (bid 0..1023, 64x64 tiles, 4 elem/thread = MLP 4),
// then gn (1024..1535), then x0 (1536..2559). prep-first ordering per R13.
// ---------------------------------------------------------------------------
#define PRO_PREP 1024
#define PRO_GN   (PRO_PREP + 512)    // 1536
#define PRO_TOT  (PRO_GN + 1024)     // 2560

__global__ __launch_bounds__(1024) void prologue(const float* __restrict__ sc,
                                                 const float* __restrict__ U,
                                                 const float* __restrict__ y,
                                                 const float* __restrict__ gw,
                                                 const float* __restrict__ gb,
                                                 const float* __restrict__ x)
{
    const int bid = blockIdx.x;
    const int tid = threadIdx.x;

    if (bid < PRO_PREP) {
        // ----- prep_K 64x64: symmetric tiles, 2x2 micro-tile per thread -----
        const int n0 = (bid >> 5) * 64, m0 = (bid & 31) * 64;
        if (m0 < n0) return;

        __shared__ float Un[64][17];
        __shared__ float Um[64][17];
        __shared__ float tT[64][65];
        __shared__ float vS[64][65];

        const int tx = tid & 31, ty = tid >> 5;

        // stage U rows: 64 rows x 16 each = 1024 entries per array
        Un[tid >> 4][tid & 15] = U[(n0 + (tid >> 4)) * RANK + (tid & 15)];
        Um[tid >> 4][tid & 15] = U[(m0 + (tid >> 4)) * RANK + (tid & 15)];
        __syncthreads();

        // 4 sigmoids per thread: a[i][j] for (n0+ty+32i, m0+tx+32j)
        float a[2][2];
#pragma unroll
        for (int i = 0; i < 2; i++)
#pragma unroll
            for (int j = 0; j < 2; j++) {
                float d = 0.f;
#pragma unroll
                for (int k = 0; k < RANK; k++)
                    d += Un[ty + 32 * i][k] * Um[tx + 32 * j][k];
                a[i][j] = 1.f / (1.f + __expf(-d));
            }

#pragma unroll 1
        for (int b = 0; b < BATCH; b++) {
            const size_t base = (size_t)b * NN * NN;
            float dv[2][2];
            // 8 independent loads in flight (MLP=8)
#pragma unroll
            for (int i = 0; i < 2; i++)
#pragma unroll
                for (int j = 0; j < 2; j++) {
                    tT[ty + 32 * i][tx + 32 * j] =
                        sc[base + (size_t)(m0 + ty + 32 * i) * NN + n0 + tx + 32 * j];
                    dv[i][j] =
                        sc[base + (size_t)(n0 + ty + 32 * i) * NN + m0 + tx + 32 * j];
                }
            __syncthreads();
#pragma unroll
            for (int i = 0; i < 2; i++)
#pragma unroll
                for (int j = 0; j < 2; j++) {
                    const int r = ty + 32 * i, c = tx + 32 * j;
                    const float v = 0.5f * (dv[i][j] + tT[c][r]) * a[i][j];
                    __half hi = __float2half_rn(v);
                    __half lo = __float2half_rn(v - __half2float(hi));
                    const size_t o1 = base + (size_t)(n0 + r) * NN + m0 + c;
                    g_Khi[o1] = hi; g_Klo[o1] = lo;
                    vS[r][c] = v;
                }
            __syncthreads();
            if (m0 != n0) {
#pragma unroll
                for (int i = 0; i < 2; i++)
#pragma unroll
                    for (int j = 0; j < 2; j++) {
                        const int r = ty + 32 * i, c = tx + 32 * j;
                        const float vt = vS[c][r];   // value at (n0+c, m0+r)
                        __half hi2 = __float2half_rn(vt);
                        __half lo2 = __float2half_rn(vt - __half2float(hi2));
                        const size_t o2 = base + (size_t)(m0 + r) * NN + n0 + c;
                        g_Khi[o2] = hi2; g_Klo[o2] = lo2;
                    }
            }
            // next batch's tT writes happen after the compute-phase sync;
            // vS reads above are ordered before next vS writes by that sync.
        }
    } else if (bid < PRO_GN) {
        // ----- gn_sphere (R13-exact): GroupNorm (4ch x 2048) per (b,g) -----
        const int gb512 = bid - PRO_PREP;
        const int b = gb512 >> 6;
        const int g = gb512 & 63;
        const float* yg = y + ((size_t)b * CC + g * 4) * NN;

        float s = 0.f, s2 = 0.f;
        for (int i = tid; i < 4 * NN; i += 1024) { float v = yg[i]; s += v; s2 += v * v; }
        __shared__ float shs[32], shs2[32];
#pragma unroll
        for (int o = 16; o; o >>= 1) {
            s  += __shfl_down_sync(0xffffffffu, s,  o);
            s2 += __shfl_down_sync(0xffffffffu, s2, o);
        }
        if ((tid & 31) == 0) { shs[tid >> 5] = s; shs2[tid >> 5] = s2; }
        __syncthreads();
        if (tid == 0) {
            float ts = 0.f, ts2 = 0.f;
#pragma unroll
            for (int i = 0; i < 32; i++) { ts += shs[i]; ts2 += shs2[i]; }
            shs[0] = ts; shs2[0] = ts2;
        }
        __syncthreads();
        const float mu   = shs[0] * (1.f / (4 * NN));
        const float var  = shs2[0] * (1.f / (4 * NN)) - mu * mu;
        const float rstd = rsqrtf(var + EPS_GN);

        float w[4], bb[4];
#pragma unroll
        for (int j = 0; j < 4; j++) { w[j] = gw[g * 4 + j]; bb[j] = gb[g * 4 + j]; }

        for (int n = tid; n < NN; n += 1024) {
            float v[4];
#pragma unroll
            for (int j = 0; j < 4; j++)
                v[j] = (yg[j * NN + n] - mu) * rstd * w[j] + bb[j];
            float n2 = fmaxf(v[0]*v[0] + v[1]*v[1] + v[2]*v[2] + v[3]*v[3], EPS_SPHERE);
            float r = rsqrtf(n2);
            *(float4*)&g_ys[((size_t)b * NN + n) * CC + g * 4] =
                make_float4(v[0]*r, v[1]*r, v[2]*r, v[3]*r);
        }
    } else {
        // ----- sphere_x0: one thread per 4-group; resets barriers -----
        const int xb = bid - PRO_GN;                     // 0..1023
        if (xb == 0 && tid < BATCH) g_barr[tid] = 0;     // graph-replay reset
        const int idx = xb * 1024 + tid;
        float4 v = ((const float4*)x)[idx];
        float n2 = fmaxf(v.x*v.x + v.y*v.y + v.z*v.z + v.w*v.w, EPS_SPHERE);
        float rs = rsqrtf(n2);
        float o0 = v.x*rs, o1 = v.y*rs, o2 = v.z*rs, o3 = v.w*rs;
        ((float4*)g_x0)[idx] = make_float4(o0, o1, o2, o3);
        __half2 hh0 = __halves2half2(__float2half_rn(o0), __float2half_rn(o1));
        __half2 hh1 = __halves2half2(__float2half_rn(o2), __float2half_rn(o3));
        ((__half2*)g_xhb[0])[idx * 2]     = hh0;
        ((__half2*)g_xhb[0])[idx * 2 + 1] = hh1;
    }
}

// ---------------------------------------------------------------------------
// step_all (R13-exact, plateau 712-717 us): all 8 steps, persistent, 128 CTAs.
// M-tile 128 x N=256, BK=64; 16 warps, warp tile 64x32; B-frag double buffer;
// gmem prefetch after kk=0; per-batch grid barrier.
// ---------------------------------------------------------------------------
#define BK 64
#define OFF_AHI 0
#define OFF_ALO 16384
#define OFF_BHI 32768
#define STAGE   65536
#define NSTAGE  3
#define SMEM_TOTAL (NSTAGE * STAGE)   // 196608
#define CS_STRIDE 264

__global__ __launch_bounds__(512, 1) void step_all(float* __restrict__ out,
                                                   const float* __restrict__ omega,
                                                   const float* __restrict__ gammap)
{
    extern __shared__ __align__(16) char dsm[];
    const uint32_t smem = smem_u32(dsm);
    const int tid  = threadIdx.x;
    const int lane = tid & 31;
    const int wid  = tid >> 5;
    const int wm   = wid & 1;
    const int wn   = wid >> 1;
    const int b    = blockIdx.y;
    const int row0 = blockIdx.x * 128;
    const size_t E = (size_t)BATCH * NN * CC;

    const __half* __restrict__ Ah = g_Khi + (size_t)b * NN * NN + (size_t)row0 * NN;
    const __half* __restrict__ Al = g_Klo + (size_t)b * NN * NN + (size_t)row0 * NN;

    auto load_A = [&](int chunk, int buf) {
        const uint32_t sb = smem + buf * STAGE;
        const int k0 = chunk * BK;
#pragma unroll
        for (int it = 0; it < 2; it++) {
            int idx = tid + it * 512;
            int m = idx >> 3, ck = idx & 7;
            uint32_t off = m * 128 + ((ck ^ (m & 7)) << 4);
            const size_t go = (size_t)m * NN + k0 + ck * 8;
            cp16(sb + OFF_AHI + off, Ah + go);
            cp16(sb + OFF_ALO + off, Al + go);
        }
        CP_COMMIT();
    };
    auto load_B = [&](int chunk, int buf, const __half* __restrict__ Bh) {
        const uint32_t sb = smem + buf * STAGE;
        const int k0 = chunk * BK;
#pragma unroll
        for (int it = 0; it < 4; it++) {
            int idx = tid + it * 512;
            int kr = idx >> 5, nc = idx & 31;
            uint32_t off = kr * 512 + ((nc ^ (kr & 7)) << 4);
            const size_t go = (size_t)(k0 + kr) * CC + nc * 8;
            cp16(sb + OFF_BHI + off, Bh + go);
        }
        CP_COMMIT();
    };
    auto load_full = [&](int chunk, int buf, const __half* __restrict__ Bh) {
        const uint32_t sb = smem + buf * STAGE;
        const int k0 = chunk * BK;
#pragma unroll
        for (int it = 0; it < 2; it++) {
            int idx = tid + it * 512;
            int m = idx >> 3, ck = idx & 7;
            uint32_t off = m * 128 + ((ck ^ (m & 7)) << 4);
            const size_t go = (size_t)m * NN + k0 + ck * 8;
            cp16(sb + OFF_AHI + off, Ah + go);
            cp16(sb + OFF_ALO + off, Al + go);
        }
#pragma unroll
        for (int it = 0; it < 4; it++) {
            int idx = tid + it * 512;
            int kr = idx >> 5, nc = idx & 31;
            uint32_t off = kr * 512 + ((nc ^ (kr & 7)) << 4);
            const size_t go = (size_t)(k0 + kr) * CC + nc * 8;
            cp16(sb + OFF_BHI + off, Bh + go);
        }
        CP_COMMIT();
    };

    const float gamma = *gammap;
    const int c = lane * 8;
    const float og0 = fabsf(omega[(c >> 1) + 0]);
    const float og1 = fabsf(omega[(c >> 1) + 1]);
    const float og2 = fabsf(omega[(c >> 1) + 2]);
    const float og3 = fabsf(omega[(c >> 1) + 3]);
    const float* __restrict__ Yg = g_ys + (size_t)b * NN * CC;

    load_A(0, 0);
    load_A(1, 1);

#pragma unroll 1
    for (int q = 0; q < QSTEPS; q++) {
        const __half* __restrict__ Bh = g_xhb[q & 1] + (size_t)b * NN * CC;
        load_B(0, 0, Bh);
        load_B(1, 1, Bh);

        float acc[4][4][4];
#pragma unroll
        for (int i = 0; i < 4; i++)
#pragma unroll
            for (int j = 0; j < 4; j++)
#pragma unroll
                for (int k = 0; k < 4; k++) acc[i][j][k] = 0.f;

#pragma unroll 1
        for (int i = 0; i < 32; i++) {
            const int buf = i - (i / NSTAGE) * NSTAGE;
            if (i < 31) CP_WAIT(1); else CP_WAIT(0);
            __syncthreads();

            const uint32_t sA  = smem + buf * STAGE + OFF_AHI;
            const uint32_t sAl = smem + buf * STAGE + OFF_ALO;
            const uint32_t sB  = smem + buf * STAGE + OFF_BHI;

            uint32_t bhb[2][2][4];
#pragma unroll
            for (int nf2 = 0; nf2 < 2; nf2++) {
                const int kr = (lane & 15);
                const int nc = wn * 4 + nf2 * 2 + (lane >> 4);
                const uint32_t off = kr * 512 + ((nc ^ (kr & 7)) << 4);
                LDSM_X4T(bhb[0][nf2][0], bhb[0][nf2][1],
                         bhb[0][nf2][2], bhb[0][nf2][3], sB + off);
            }

#pragma unroll
            for (int kk = 0; kk < 4; kk++) {
                const int cur = kk & 1;
                if (kk < 3) {
#pragma unroll
                    for (int nf2 = 0; nf2 < 2; nf2++) {
                        const int kr = (kk + 1) * 16 + (lane & 15);
                        const int nc = wn * 4 + nf2 * 2 + (lane >> 4);
                        const uint32_t off = kr * 512 + ((nc ^ (kr & 7)) << 4);
                        LDSM_X4T(bhb[cur ^ 1][nf2][0], bhb[cur ^ 1][nf2][1],
                                 bhb[cur ^ 1][nf2][2], bhb[cur ^ 1][nf2][3], sB + off);
                    }
                }
#pragma unroll
                for (int mf = 0; mf < 4; mf++) {
                    const int m = wm * 64 + mf * 16 + (lane & 15);
                    const int kc = kk * 2 + (lane >> 4);
                    const uint32_t off = m * 128 + ((kc ^ (m & 7)) << 4);
                    uint32_t ah0, ah1, ah2, ah3, al0, al1, al2, al3;
                    LDSM_X4(ah0, ah1, ah2, ah3, sA  + off);
                    LDSM_X4(al0, al1, al2, al3, sAl + off);
#pragma unroll
                    for (int nf2 = 0; nf2 < 2; nf2++) {
#pragma unroll
                        for (int j = 0; j < 2; j++) {
                            float* d = acc[mf][nf2 * 2 + j];
                            MMA16816(d, ah0, ah1, ah2, ah3,
                                     bhb[cur][nf2][j*2], bhb[cur][nf2][j*2+1]);
                            MMA16816(d, al0, al1, al2, al3,
                                     bhb[cur][nf2][j*2], bhb[cur][nf2][j*2+1]);
                        }
                    }
                }
                if (kk == 0 && i + 2 < 32) {
                    int nb = (i + 2) - ((i + 2) / NSTAGE) * NSTAGE;
                    load_full(i + 2, nb, Bh);
                }
            }
        }
        __syncthreads();

        float* cs = (float*)dsm;
#pragma unroll
        for (int mf = 0; mf < 4; mf++)
#pragma unroll
            for (int mh = 0; mh < 2; mh++)
#pragma unroll
                for (int nf = 0; nf < 4; nf++) {
                    const int row = wm * 64 + mf * 16 + mh * 8 + (lane >> 2);
                    const int col = wn * 32 + nf * 8 + (lane & 3) * 2;
                    *(float2*)&cs[row * CS_STRIDE + col] =
                        make_float2(acc[mf][nf][mh * 2], acc[mf][nf][mh * 2 + 1]);
                }
        __syncthreads();

        const float* __restrict__ Xg = (q == 0 ? g_x0 : out + (size_t)(q - 1) * E)
                                       + (size_t)b * NN * CC;
        float* __restrict__ Og = out + (size_t)q * E + (size_t)b * NN * CC;
        __half* __restrict__ XHg = g_xhb[(q + 1) & 1] + (size_t)b * NN * CC;

#pragma unroll 1
        for (int rr = 0; rr < 8; rr++) {
            const int lr = wid * 8 + rr;
            const size_t goff = (size_t)(row0 + lr) * CC + c;
            float4 k0 = *(const float4*)&cs[lr * CS_STRIDE + c];
            float4 k1 = *(const float4*)&cs[lr * CS_STRIDE + c + 4];
            float4 x0 = *(const float4*)&Xg[goff];
            float4 x1 = *(const float4*)&Xg[goff + 4];
            float4 y0 = *(const float4*)&Yg[goff];
            float4 y1 = *(const float4*)&Yg[goff + 4];

            float ox[8];
            {
                float f0 = k0.x + y0.x, f1 = k0.y + y0.y, f2 = k0.z + y0.z, f3 = k0.w + y0.w;
                float sim = x0.x*f0 + x0.y*f1 + x0.z*f2 + x0.w*f3;
                float d0 =  og0 * x0.y + (f0 - sim * x0.x);
                float d1 = -og0 * x0.x + (f1 - sim * x0.y);
                float d2 =  og1 * x0.w + (f2 - sim * x0.z);
                float d3 = -og1 * x0.z + (f3 - sim * x0.w);
                float u0 = x0.x + gamma * d0, u1 = x0.y + gamma * d1;
                float u2 = x0.z + gamma * d2, u3 = x0.w + gamma * d3;
                float rs = rsqrtf(fmaxf(u0*u0 + u1*u1 + u2*u2 + u3*u3, EPS_SPHERE));
                ox[0] = u0*rs; ox[1] = u1*rs; ox[2] = u2*rs; ox[3] = u3*rs;
            }
            {
                float f0 = k1.x + y1.x, f1 = k1.y + y1.y, f2 = k1.z + y1.z, f3 = k1.w + y1.w;
                float sim = x1.x*f0 + x1.y*f1 + x1.z*f2 + x1.w*f3;
                float d0 =  og2 * x1.y + (f0 - sim * x1.x);
                float d1 = -og2 * x1.x + (f1 - sim * x1.y);
                float d2 =  og3 * x1.w + (f2 - sim * x1.z);
                float d3 = -og3 * x1.z + (f3 - sim * x1.w);
                float u0 = x1.x + gamma * d0, u1 = x1.y + gamma * d1;
                float u2 = x1.z + gamma * d2, u3 = x1.w + gamma * d3;
                float rs = rsqrtf(fmaxf(u0*u0 + u1*u1 + u2*u2 + u3*u3, EPS_SPHERE));
                ox[4] = u0*rs; ox[5] = u1*rs; ox[6] = u2*rs; ox[7] = u3*rs;
            }
            *(float4*)&Og[goff]     = make_float4(ox[0], ox[1], ox[2], ox[3]);
            *(float4*)&Og[goff + 4] = make_float4(ox[4], ox[5], ox[6], ox[7]);

            if (q < QSTEPS - 1) {
                uint32_t hw[4];
#pragma unroll
                for (int j = 0; j < 4; j++) {
                    __half2 p = __halves2half2(__float2half_rn(ox[2*j]),
                                               __float2half_rn(ox[2*j+1]));
                    hw[j] = *(uint32_t*)&p;
                }
                *(uint4*)&XHg[goff] = make_uint4(hw[0], hw[1], hw[2], hw[3]);
            }
        }

        if (q < QSTEPS - 1) {
            __syncthreads();
            load_A(0, 0);
            load_A(1, 1);
            if (tid == 0) {                  // per-batch barrier (16 CTAs)
                unsigned* bar = &g_barr[b];
                asm volatile("red.release.gpu.global.add.u32 [%0], 1;"
                             :: "l"(bar) : "memory");
                const unsigned target = (unsigned)(q + 1) * CTA_PER_BATCH;
                unsigned v;
                do {
                    asm volatile("ld.acquire.gpu.global.u32 %0, [%1];"
                                 : "=r"(v) : "l"(bar) : "memory");
                } while (v < target);
            }
            __syncthreads();
        }
    }
}

// ---------------------------------------------------------------------------
// Launch. Inputs: x, y, sc, U, omega_param, gn_w, gn_b, gamma, Q.
// Output: xs [Q=8, B, N, C] fp32.
// ---------------------------------------------------------------------------
extern "C" void kernel_launch(void* const* d_in, const int* in_sizes, int n_in,
                              void* d_out, int out_size)
{
    const float* x     = (const float*)d_in[0];
    const float* y     = (const float*)d_in[1];
    const float* sc    = (const float*)d_in[2];
    const float* U     = (const float*)d_in[3];
    const float* omega = (const float*)d_in[4];
    const float* gw    = (const float*)d_in[5];
    const float* gb    = (const float*)d_in[6];
    const float* gamma = (const float*)d_in[7];
    float* out = (float*)d_out;

    static int attr_set = 0;
    if (!attr_set) {
        cudaFuncSetAttribute(step_all, cudaFuncAttributeMaxDynamicSharedMemorySize,
                             SMEM_TOTAL);
        attr_set = 1;
    }

    prologue<<<PRO_TOT, 1024>>>(sc, U, y, gw, gb, x);
    step_all<<<dim3(16, BATCH), 512, SMEM_TOTAL>>>(out, omega, gamma);
}